// round 12
// baseline (speedup 1.0000x reference)
#include <cuda_runtime.h>
#include <cuda_fp16.h>

#define N_ENT   100000
#define N_EDGE  1600000
#define N_REL   64
#define NB_SCAN ((N_ENT + 255) / 256)    // 391

// Scratch (allocation-free rule: __device__ globals)
static __device__ float  g_tailproj[N_ENT * 64];   // W_t · emb[n]           (fp32)
static __device__ __half g_headrec [N_ENT * 128];  // [W_h·emb | M_h·emb]    (fp16)
static __device__ float  g_relcat  [N_REL * 128];  // [W_r·emb_rel+b | M_r·emb_rel]
static __device__ int    g_deg     [N_ENT];        // in-degree (excl. self)
static __device__ int    g_off     [N_ENT + 1];    // CSR offsets
static __device__ int    g_cursor  [N_ENT];        // scatter cursors
static __device__ int    g_bsum    [NB_SCAN];      // scan block sums
static __device__ int    g_boff    [NB_SCAN];      // scan block offsets
static __device__ int    g_sortkey [N_EDGE];       // head | rel<<17, grouped by tail

typedef unsigned long long u64;

__device__ __forceinline__ u64 pack2(float lo, float hi) {
    u64 r;
    asm("mov.b64 %0, {%1, %2};" : "=l"(r) : "f"(lo), "f"(hi));
    return r;
}
__device__ __forceinline__ void unpack2(u64 v, float& lo, float& hi) {
    asm("mov.b64 {%0, %1}, %2;" : "=f"(lo), "=f"(hi) : "l"(v));
}
__device__ __forceinline__ u64 fma2(u64 a, u64 b, u64 c) {
    u64 d;
    asm("fma.rn.f32x2 %0, %1, %2, %3;" : "=l"(d) : "l"(a), "l"(b), "l"(c));
    return d;
}

// ---------------------------------------------------------------------------
// Per-relation table: relcat[r] = [W_r·emb_rel[r] + attn_b | M_r·emb_rel[r]]
__global__ void rel_tables_kernel(const float* __restrict__ emb_rel,
                                  const float* __restrict__ attn_W,
                                  const float* __restrict__ attn_b,
                                  const float* __restrict__ aggr_W) {
    int r = threadIdx.x;
    if (r >= N_REL) return;
    float ev[32];
#pragma unroll
    for (int k = 0; k < 32; k++) ev[k] = emb_rel[r * 32 + k];
    for (int o = 0; o < 64; o++) {
        float a = attn_b[o], m = 0.f;
#pragma unroll
        for (int k = 0; k < 32; k++) {
            a = fmaf(attn_W[o * 96 + 64 + k], ev[k], a);
            m = fmaf(aggr_W[o * 64 + 32 + k], ev[k], m);
        }
        g_relcat[r * 128 + o]      = a;
        g_relcat[r * 128 + 64 + o] = m;
    }
}

// ---------------------------------------------------------------------------
__global__ void deg_kernel(const int* __restrict__ tail) {
    int e = blockIdx.x * blockDim.x + threadIdx.x;
    if (e < N_EDGE) atomicAdd(&g_deg[tail[e]], 1);
}

// ---------------------------------------------------------------------------
// 3-phase multi-block exclusive scan over degrees
__global__ void scanA_kernel() {
    __shared__ int s[256];
    int n = blockIdx.x * 256 + threadIdx.x;
    s[threadIdx.x] = (n < N_ENT) ? g_deg[n] : 0;
    __syncthreads();
    for (int o = 128; o > 0; o >>= 1) {
        if (threadIdx.x < o) s[threadIdx.x] += s[threadIdx.x + o];
        __syncthreads();
    }
    if (threadIdx.x == 0) g_bsum[blockIdx.x] = s[0];
}
__global__ void scanB_kernel() {
    __shared__ int s[512];
    int tid = threadIdx.x;
    s[tid] = (tid < NB_SCAN) ? g_bsum[tid] : 0;
    __syncthreads();
    for (int d = 1; d < 512; d <<= 1) {
        int v = (tid >= d) ? s[tid - d] : 0;
        __syncthreads();
        s[tid] += v;
        __syncthreads();
    }
    if (tid < NB_SCAN) g_boff[tid] = tid ? s[tid - 1] : 0;
    if (tid == 511) g_off[N_ENT] = s[NB_SCAN - 1];
}
__global__ void scanC_kernel() {
    __shared__ int s[256];
    int n = blockIdx.x * 256 + threadIdx.x;
    int d = (n < N_ENT) ? g_deg[n] : 0;
    s[threadIdx.x] = d;
    __syncthreads();
    for (int o = 1; o < 256; o <<= 1) {
        int v = (threadIdx.x >= o) ? s[threadIdx.x - o] : 0;
        __syncthreads();
        s[threadIdx.x] += v;
        __syncthreads();
    }
    if (n < N_ENT) {
        int off = g_boff[blockIdx.x] + s[threadIdx.x] - d;   // exclusive
        g_off[n]    = off;
        g_cursor[n] = off;
    }
}

// ---------------------------------------------------------------------------
__global__ void scatter_kernel(const int* __restrict__ head,
                               const int* __restrict__ tail,
                               const int* __restrict__ rel) {
    int e = blockIdx.x * blockDim.x + threadIdx.x;
    if (e >= N_EDGE) return;
    int pos = atomicAdd(&g_cursor[tail[e]], 1);
    g_sortkey[pos] = head[e] | (rel[e] << 17);
}

// ---------------------------------------------------------------------------
// Per-node projections (3 GEMVs fused): 4 nodes per warp per k-step, weights
// packed as (o=lane, o=lane+32) float2 pairs -> LDS.64 + fma.rn.f32x2.
__global__ void __launch_bounds__(256) node_proj_kernel(
        const float* __restrict__ emb_ent,
        const float* __restrict__ attn_W,
        const float* __restrict__ aggr_W) {
    __shared__ float2 s_w[3][32 * 32];   // 24KB
    for (int i = threadIdx.x; i < 1024; i += blockDim.x) {
        int k = i >> 5, l = i & 31;
        s_w[0][i] = make_float2(attn_W[l * 96 + k],      attn_W[(l + 32) * 96 + k]);
        s_w[1][i] = make_float2(attn_W[l * 96 + 32 + k], attn_W[(l + 32) * 96 + 32 + k]);
        s_w[2][i] = make_float2(aggr_W[l * 64 + k],      aggr_W[(l + 32) * 64 + k]);
    }
    __syncthreads();

    int lane = threadIdx.x & 31;
    int gw   = blockIdx.x * (blockDim.x >> 5) + (threadIdx.x >> 5);
    int GW   = gridDim.x * (blockDim.x >> 5);

    for (int base = gw * 4; base < N_ENT; base += GW * 4) {   // N_ENT % 4 == 0
        float e0 = emb_ent[(base + 0) * 32 + lane];
        float e1 = emb_ent[(base + 1) * 32 + lane];
        float e2 = emb_ent[(base + 2) * 32 + lane];
        float e3 = emb_ent[(base + 3) * 32 + lane];

        u64 A[4], B[4], M[4];
#pragma unroll
        for (int i = 0; i < 4; i++) { A[i] = 0; B[i] = 0; M[i] = 0; }

#pragma unroll
        for (int k = 0; k < 32; k++) {
            u64 w0 = *(const u64*)&s_w[0][k * 32 + lane];
            u64 w1 = *(const u64*)&s_w[1][k * 32 + lane];
            u64 w2 = *(const u64*)&s_w[2][k * 32 + lane];
            float ek[4];
            ek[0] = __shfl_sync(0xffffffffu, e0, k);
            ek[1] = __shfl_sync(0xffffffffu, e1, k);
            ek[2] = __shfl_sync(0xffffffffu, e2, k);
            ek[3] = __shfl_sync(0xffffffffu, e3, k);
#pragma unroll
            for (int i = 0; i < 4; i++) {
                u64 ekk = pack2(ek[i], ek[i]);
                A[i] = fma2(w0, ekk, A[i]);
                B[i] = fma2(w1, ekk, B[i]);
                M[i] = fma2(w2, ekk, M[i]);
            }
        }

#pragma unroll
        for (int i = 0; i < 4; i++) {
            int n = base + i;
            float lo, hi;
            unpack2(A[i], lo, hi);
            g_tailproj[n * 64 + lane]      = lo;
            g_tailproj[n * 64 + 32 + lane] = hi;
            unpack2(B[i], lo, hi);
            g_headrec[n * 128 + lane]      = __float2half_rn(lo);
            g_headrec[n * 128 + 32 + lane] = __float2half_rn(hi);
            unpack2(M[i], lo, hi);
            g_headrec[n * 128 + 64 + lane] = __float2half_rn(lo);
            g_headrec[n * 128 + 96 + lane] = __float2half_rn(hi);
        }
    }
}

// ---------------------------------------------------------------------------
// Fused CSR aggregate, head-per-lane layout: lane h owns the 8 dims of head
// (lane&7); 4 edge-groups of 8 lanes per warp -> 4 edges in flight, ZERO
// shuffles in the edge loop (logit dot is lane-local). Self record = mean of
// relcat rows (accumulated in-loop). Direct output write. Zero atomics.
__global__ void __launch_bounds__(256) aggregate_kernel(
        const float* __restrict__ attn_vec,
        const float* __restrict__ aggr_b,
        float* __restrict__ out) {
    __shared__ float4 s_rel[N_REL * 32];   // 32KB: row r = 32 float4s
    {
        const float4* src = (const float4*)g_relcat;
        for (int i = threadIdx.x; i < N_REL * 32; i += blockDim.x)
            s_rel[i] = src[i];
    }
    __syncthreads();

    int lane = threadIdx.x & 31;
    int h    = lane & 7;      // head index (owns dims 8h..8h+7)
    int grp  = lane >> 3;     // edge sub-group 0..3
    int gw = blockIdx.x * (blockDim.x >> 5) + (threadIdx.x >> 5);
    int GW = gridDim.x * (blockDim.x >> 5);

    float4 v0 = *(const float4*)(&attn_vec[8 * h]);
    float4 v1 = *(const float4*)(&attn_vec[8 * h + 4]);

    for (int n = gw; n < N_ENT; n += GW) {
        int beg = g_off[n], end = g_off[n + 1];
        float4 at0 = *(const float4*)(&g_tailproj[n * 64 + 8 * h]);
        float4 at1 = *(const float4*)(&g_tailproj[n * 64 + 8 * h + 4]);

        float acc[8] = {0, 0, 0, 0, 0, 0, 0, 0};
        float scr[8] = {0, 0, 0, 0, 0, 0, 0, 0};
        float smm[8] = {0, 0, 0, 0, 0, 0, 0, 0};
        float den = 0.f;

        for (int i = beg + grp; i < end; i += 4) {
            int x  = g_sortkey[i];
            int hn = x & 0x1FFFF;
            int r  = x >> 17;
            const __half* hp = &g_headrec[hn * 128 + 8 * h];
            uint4 ua = *(const uint4*)hp;          // 8 halves: attn dims
            uint4 um = *(const uint4*)(hp + 64);   // 8 halves: msg dims
            float2 a0 = __half22float2(*reinterpret_cast<__half2*>(&ua.x));
            float2 a1 = __half22float2(*reinterpret_cast<__half2*>(&ua.y));
            float2 a2 = __half22float2(*reinterpret_cast<__half2*>(&ua.z));
            float2 a3 = __half22float2(*reinterpret_cast<__half2*>(&ua.w));
            float2 m0 = __half22float2(*reinterpret_cast<__half2*>(&um.x));
            float2 m1 = __half22float2(*reinterpret_cast<__half2*>(&um.y));
            float2 m2 = __half22float2(*reinterpret_cast<__half2*>(&um.z));
            float2 m3 = __half22float2(*reinterpret_cast<__half2*>(&um.w));
            float4 cr0 = s_rel[r * 32 + 2 * h];
            float4 cr1 = s_rel[r * 32 + 2 * h + 1];
            float4 mm0 = s_rel[r * 32 + 16 + 2 * h];
            float4 mm1 = s_rel[r * 32 + 16 + 2 * h + 1];

            scr[0] += cr0.x; scr[1] += cr0.y; scr[2] += cr0.z; scr[3] += cr0.w;
            scr[4] += cr1.x; scr[5] += cr1.y; scr[6] += cr1.z; scr[7] += cr1.w;
            smm[0] += mm0.x; smm[1] += mm0.y; smm[2] += mm0.z; smm[3] += mm0.w;
            smm[4] += mm1.x; smm[5] += mm1.y; smm[6] += mm1.z; smm[7] += mm1.w;

            float p0 = at0.x + a0.x + cr0.x; p0 = fmaxf(p0, 0.2f * p0);
            float p1 = at0.y + a0.y + cr0.y; p1 = fmaxf(p1, 0.2f * p1);
            float p2 = at0.z + a1.x + cr0.z; p2 = fmaxf(p2, 0.2f * p2);
            float p3 = at0.w + a1.y + cr0.w; p3 = fmaxf(p3, 0.2f * p3);
            float p4 = at1.x + a2.x + cr1.x; p4 = fmaxf(p4, 0.2f * p4);
            float p5 = at1.y + a2.y + cr1.y; p5 = fmaxf(p5, 0.2f * p5);
            float p6 = at1.z + a3.x + cr1.z; p6 = fmaxf(p6, 0.2f * p6);
            float p7 = at1.w + a3.y + cr1.w; p7 = fmaxf(p7, 0.2f * p7);
            float s = ((p0 * v0.x + p1 * v0.y) + (p2 * v0.z + p3 * v0.w))
                    + ((p4 * v1.x + p5 * v1.y) + (p6 * v1.z + p7 * v1.w));
            float ex = __expf(s);                  // lane-local: no shuffle!

            acc[0] = fmaf(ex, m0.x + mm0.x, acc[0]);
            acc[1] = fmaf(ex, m0.y + mm0.y, acc[1]);
            acc[2] = fmaf(ex, m1.x + mm0.z, acc[2]);
            acc[3] = fmaf(ex, m1.y + mm0.w, acc[3]);
            acc[4] = fmaf(ex, m2.x + mm1.x, acc[4]);
            acc[5] = fmaf(ex, m2.y + mm1.y, acc[5]);
            acc[6] = fmaf(ex, m3.x + mm1.z, acc[6]);
            acc[7] = fmaf(ex, m3.y + mm1.w, acc[7]);
            den += ex;
        }

        // combine the 4 edge-groups (lanes with equal h)
#pragma unroll
        for (int off = 8; off <= 16; off <<= 1) {
#pragma unroll
            for (int j = 0; j < 8; j++) {
                acc[j] += __shfl_xor_sync(0xffffffffu, acc[j], off);
                scr[j] += __shfl_xor_sync(0xffffffffu, scr[j], off);
                smm[j] += __shfl_xor_sync(0xffffffffu, smm[j], off);
            }
            den += __shfl_xor_sync(0xffffffffu, den, off);
        }

        if (grp == 0) {
            // self record = mean of relcat rows; self-loop + normalize + bias
            float invd = 1.f / (float)(end - beg);
            const __half* hp = &g_headrec[n * 128 + 8 * h];
            uint4 ua = *(const uint4*)hp;
            uint4 um = *(const uint4*)(hp + 64);
            float2 a0 = __half22float2(*reinterpret_cast<__half2*>(&ua.x));
            float2 a1 = __half22float2(*reinterpret_cast<__half2*>(&ua.y));
            float2 a2 = __half22float2(*reinterpret_cast<__half2*>(&ua.z));
            float2 a3 = __half22float2(*reinterpret_cast<__half2*>(&ua.w));
            float2 m0 = __half22float2(*reinterpret_cast<__half2*>(&um.x));
            float2 m1 = __half22float2(*reinterpret_cast<__half2*>(&um.y));
            float2 m2 = __half22float2(*reinterpret_cast<__half2*>(&um.z));
            float2 m3 = __half22float2(*reinterpret_cast<__half2*>(&um.w));

            float p0 = at0.x + a0.x + scr[0] * invd; p0 = fmaxf(p0, 0.2f * p0);
            float p1 = at0.y + a0.y + scr[1] * invd; p1 = fmaxf(p1, 0.2f * p1);
            float p2 = at0.z + a1.x + scr[2] * invd; p2 = fmaxf(p2, 0.2f * p2);
            float p3 = at0.w + a1.y + scr[3] * invd; p3 = fmaxf(p3, 0.2f * p3);
            float p4 = at1.x + a2.x + scr[4] * invd; p4 = fmaxf(p4, 0.2f * p4);
            float p5 = at1.y + a2.y + scr[5] * invd; p5 = fmaxf(p5, 0.2f * p5);
            float p6 = at1.z + a3.x + scr[6] * invd; p6 = fmaxf(p6, 0.2f * p6);
            float p7 = at1.w + a3.y + scr[7] * invd; p7 = fmaxf(p7, 0.2f * p7);
            float s = ((p0 * v0.x + p1 * v0.y) + (p2 * v0.z + p3 * v0.w))
                    + ((p4 * v1.x + p5 * v1.y) + (p6 * v1.z + p7 * v1.w));
            float ex = __expf(s);

            float inv = 1.f / (den + ex + 1e-16f);
            float4 b0 = *(const float4*)(&aggr_b[8 * h]);
            float4 b1 = *(const float4*)(&aggr_b[8 * h + 4]);
            float4 o0, o1;
            o0.x = fmaf(fmaf(ex, m0.x + smm[0] * invd, acc[0]), inv, b0.x);
            o0.y = fmaf(fmaf(ex, m0.y + smm[1] * invd, acc[1]), inv, b0.y);
            o0.z = fmaf(fmaf(ex, m1.x + smm[2] * invd, acc[2]), inv, b0.z);
            o0.w = fmaf(fmaf(ex, m1.y + smm[3] * invd, acc[3]), inv, b0.w);
            o1.x = fmaf(fmaf(ex, m2.x + smm[4] * invd, acc[4]), inv, b1.x);
            o1.y = fmaf(fmaf(ex, m2.y + smm[5] * invd, acc[5]), inv, b1.y);
            o1.z = fmaf(fmaf(ex, m3.x + smm[6] * invd, acc[6]), inv, b1.z);
            o1.w = fmaf(fmaf(ex, m3.y + smm[7] * invd, acc[7]), inv, b1.w);
            *(float4*)(&out[n * 64 + 8 * h])     = o0;
            *(float4*)(&out[n * 64 + 8 * h + 4]) = o1;
        }
    }
}

// ---------------------------------------------------------------------------
extern "C" void kernel_launch(void* const* d_in, const int* in_sizes, int n_in,
                              void* d_out, int out_size) {
    const float* emb_ent  = (const float*)d_in[0];
    const float* emb_rel  = (const float*)d_in[1];
    const float* attn_W   = (const float*)d_in[2];
    const float* attn_b   = (const float*)d_in[3];
    const float* attn_vec = (const float*)d_in[4];
    const float* aggr_W   = (const float*)d_in[5];
    const float* aggr_b   = (const float*)d_in[6];
    const int*   head     = (const int*)d_in[7];
    const int*   tail     = (const int*)d_in[8];
    const int*   rel      = (const int*)d_in[9];
    float*       out      = (float*)d_out;

    void* p_deg;
    cudaGetSymbolAddress(&p_deg, g_deg);
    cudaMemsetAsync(p_deg, 0, sizeof(int) * N_ENT);

    // node_proj placed 4th so the profiler window (4th kernel) lands on it
    rel_tables_kernel<<<1, 64>>>(emb_rel, attn_W, attn_b, aggr_W);
    deg_kernel<<<(N_EDGE + 255) / 256, 256>>>(tail);
    scanA_kernel<<<NB_SCAN, 256>>>();
    node_proj_kernel<<<740, 256>>>(emb_ent, attn_W, aggr_W);
    scanB_kernel<<<1, 512>>>();
    scanC_kernel<<<NB_SCAN, 256>>>();
    scatter_kernel<<<(N_EDGE + 255) / 256, 256>>>(head, tail, rel);
    aggregate_kernel<<<1036, 256>>>(attn_vec, aggr_b, out);
}